// round 10
// baseline (speedup 1.0000x reference)
#include <cuda_runtime.h>
#include <math.h>

#define BB 64
#define CC 3
#define HH 640
#define WW 640
#define PH 128
#define PW 128

struct BatchParams {
    float y0, x0, sh, sw, inv_sh, inv_sw, co, si;
};

__global__ __launch_bounds__(256) void patch_kernel(
    const float4* __restrict__ images,
    const float*  __restrict__ patch,
    const float*  __restrict__ angles,
    const float*  __restrict__ scales,
    const float*  __restrict__ ux,
    const float*  __restrict__ uy,
    float4*       __restrict__ out)
{
    constexpr int QW   = WW / 4;        // 160 quads per row
    constexpr int QIMG = HH * QW;       // 102400 quads per channel (divisible by 256)

    __shared__ BatchParams sp;

    int tid = blockIdx.x * 256 + threadIdx.x;
    int b   = blockIdx.x / (QIMG / 256);          // uniform per block
    int rem = tid - b * QIMG;
    int y   = rem / QW;
    int xq  = rem - y * QW;

    if (threadIdx.x == 0) {
        float s  = scales[b];
        float sh = floorf((float)PH * s);
        float sw = floorf((float)PW * s);
        BatchParams p;
        p.sh = sh; p.sw = sw;
        p.y0 = floorf(uy[b] * ((float)HH - sh));
        p.x0 = floorf(ux[b] * ((float)WW - sw));
        p.inv_sh = (float)PH / sh;
        p.inv_sw = (float)PW / sw;
        float th = angles[b] * (float)(M_PI / 180.0);
        p.co = cosf(th);
        p.si = sinf(th);
        sp = p;
    }
    __syncthreads();
    BatchParams p = sp;

    float yl  = (float)y - p.y0;
    float xl0 = (float)(xq * 4) - p.x0;
    bool yin  = (yl >= 0.0f) & (yl < p.sh);
    bool xin  = (xl0 + 3.0f >= 0.0f) & (xl0 < p.sw);

    int q0 = b * (CC * QIMG) + y * QW + xq;   // float4 index of channel 0

    if (!(yin & xin)) {
        // Fast path: streaming copy; evict-first loads, write-through stores
        float4 v0 = __ldcs(images + q0);
        float4 v1 = __ldcs(images + q0 + QIMG);
        float4 v2 = __ldcs(images + q0 + 2 * QIMG);
        __stwt(out + q0,            v0);
        __stwt(out + q0 + QIMG,     v1);
        __stwt(out + q0 + 2 * QIMG, v2);
        return;
    }

    // Slow path
    bool all_in = (xl0 >= 0.0f) & (xl0 + 3.0f < p.sw);

    float img[3][4];
    if (!all_in) {
        float4 v0 = __ldcs(images + q0);
        float4 v1 = __ldcs(images + q0 + QIMG);
        float4 v2 = __ldcs(images + q0 + 2 * QIMG);
        img[0][0]=v0.x; img[0][1]=v0.y; img[0][2]=v0.z; img[0][3]=v0.w;
        img[1][0]=v1.x; img[1][1]=v1.y; img[1][2]=v1.z; img[1][3]=v1.w;
        img[2][0]=v2.x; img[2][1]=v2.y; img[2][2]=v2.z; img[2][3]=v2.w;
    }
    float res[3][4];

    const float cy = (float)(PH - 1) * 0.5f;
    const float cx = (float)(PW - 1) * 0.5f;
    float yr   = (yl + 0.5f) * p.inv_sh - 0.5f;
    float dy   = yr - cy;
    float sidy = p.si * dy;
    float cody = p.co * dy;

    #pragma unroll
    for (int i = 0; i < 4; i++) {
        float xl  = xl0 + (float)i;
        bool  vld = (xl >= 0.0f) & (xl < p.sw);

        if (!vld) {
            res[0][i] = img[0][i];
            res[1][i] = img[1][i];
            res[2][i] = img[2][i];
            continue;
        }

        float xr = (xl + 0.5f) * p.inv_sw - 0.5f;
        float dx = xr - cx;
        float xp =  p.co * dx + sidy + cx;
        float yp = -p.si * dx + cody + cy;

        float fy = floorf(yp);
        float fx = floorf(xp);
        float wy = yp - fy;
        float wx = xp - fx;
        int yi = (int)fy;
        int xi = (int)fx;

        bool y0in = (yi >= 0)  & (yi <  PH);
        bool y1in = (yi >= -1) & (yi <  PH - 1);
        bool x0in = (xi >= 0)  & (xi <  PW);
        bool x1in = (xi >= -1) & (xi <  PW - 1);

        int yc0 = min(max(yi,     0), PH - 1);
        int yc1 = min(max(yi + 1, 0), PH - 1);
        int xc0 = min(max(xi,     0), PW - 1);
        int xc1 = min(max(xi + 1, 0), PW - 1);

        float w00 = (1.0f - wy) * (1.0f - wx) * ((y0in & x0in) ? 1.0f : 0.0f);
        float w01 = (1.0f - wy) * wx          * ((y0in & x1in) ? 1.0f : 0.0f);
        float w10 = wy * (1.0f - wx)          * ((y1in & x0in) ? 1.0f : 0.0f);
        float w11 = wy * wx                   * ((y1in & x1in) ? 1.0f : 0.0f);

        int o00 = yc0 * PW + xc0;
        int o01 = yc0 * PW + xc1;
        int o10 = yc1 * PW + xc0;
        int o11 = yc1 * PW + xc1;

        #pragma unroll
        for (int c = 0; c < 3; c++) {
            const float* pc = patch + c * (PH * PW);
            res[c][i] = w00 * __ldg(pc + o00)
                      + w01 * __ldg(pc + o01)
                      + w10 * __ldg(pc + o10)
                      + w11 * __ldg(pc + o11);
        }
    }

    float4 r0 = make_float4(res[0][0], res[0][1], res[0][2], res[0][3]);
    float4 r1 = make_float4(res[1][0], res[1][1], res[1][2], res[1][3]);
    float4 r2 = make_float4(res[2][0], res[2][1], res[2][2], res[2][3]);
    __stwt(out + q0,            r0);
    __stwt(out + q0 + QIMG,     r1);
    __stwt(out + q0 + 2 * QIMG, r2);
}

extern "C" void kernel_launch(void* const* d_in, const int* in_sizes, int n_in,
                              void* d_out, int out_size) {
    const float* images = (const float*)d_in[0];
    const float* patch  = (const float*)d_in[1];
    const float* angles = (const float*)d_in[2];
    const float* scales = (const float*)d_in[3];
    const float* ux     = (const float*)d_in[4];
    const float* uy     = (const float*)d_in[5];
    float* out = (float*)d_out;

    constexpr int QUADS = BB * HH * (WW / 4);   // 6,553,600
    int blocks = QUADS / 256;                   // 25,600
    patch_kernel<<<blocks, 256>>>(
        (const float4*)images, patch, angles, scales, ux, uy, (float4*)out);
}

// round 11
// speedup vs baseline: 1.0214x; 1.0214x over previous
#include <cuda_runtime.h>
#include <math.h>

#define BB 64
#define CC 3
#define HH 640
#define WW 640
#define PH 128
#define PW 128

struct BatchParams {
    float y0, x0, sh, sw, inv_sh, inv_sw, co, si;
};

__global__ __launch_bounds__(256) void patch_kernel(
    const float4* __restrict__ images,
    const float*  __restrict__ patch,
    const float*  __restrict__ angles,
    const float*  __restrict__ scales,
    const float*  __restrict__ ux,
    const float*  __restrict__ uy,
    float4*       __restrict__ out)
{
    constexpr int QW   = WW / 4;        // 160 quads per row
    constexpr int QIMG = HH * QW;       // 102400 quads per channel (divisible by 256)

    __shared__ BatchParams sp;

    int tid = blockIdx.x * 256 + threadIdx.x;
    int b   = blockIdx.x / (QIMG / 256);          // uniform per block
    int rem = tid - b * QIMG;
    int y   = rem / QW;
    int xq  = rem - y * QW;

    if (threadIdx.x == 0) {
        float s  = scales[b];
        float sh = floorf((float)PH * s);
        float sw = floorf((float)PW * s);
        BatchParams p;
        p.sh = sh; p.sw = sw;
        p.y0 = floorf(uy[b] * ((float)HH - sh));
        p.x0 = floorf(ux[b] * ((float)WW - sw));
        p.inv_sh = (float)PH / sh;
        p.inv_sw = (float)PW / sw;
        float th = angles[b] * (float)(M_PI / 180.0);
        p.co = cosf(th);
        p.si = sinf(th);
        sp = p;
    }
    __syncthreads();
    BatchParams p = sp;

    float yl  = (float)y - p.y0;
    float xl0 = (float)(xq * 4) - p.x0;
    bool yin  = (yl >= 0.0f) & (yl < p.sh);
    bool xin  = (xl0 + 3.0f >= 0.0f) & (xl0 < p.sw);

    int q0 = b * (CC * QIMG) + y * QW + xq;   // float4 index of channel 0

    if (!(yin & xin)) {
        // Fast path: streaming copy (evict-first both directions)
        float4 v0 = __ldcs(images + q0);
        float4 v1 = __ldcs(images + q0 + QIMG);
        float4 v2 = __ldcs(images + q0 + 2 * QIMG);
        __stcs(out + q0,            v0);
        __stcs(out + q0 + QIMG,     v1);
        __stcs(out + q0 + 2 * QIMG, v2);
        return;
    }

    // Slow path
    bool all_in = (xl0 >= 0.0f) & (xl0 + 3.0f < p.sw);

    float img[3][4];
    if (!all_in) {
        float4 v0 = __ldcs(images + q0);
        float4 v1 = __ldcs(images + q0 + QIMG);
        float4 v2 = __ldcs(images + q0 + 2 * QIMG);
        img[0][0]=v0.x; img[0][1]=v0.y; img[0][2]=v0.z; img[0][3]=v0.w;
        img[1][0]=v1.x; img[1][1]=v1.y; img[1][2]=v1.z; img[1][3]=v1.w;
        img[2][0]=v2.x; img[2][1]=v2.y; img[2][2]=v2.z; img[2][3]=v2.w;
    }
    float res[3][4];

    const float cy = (float)(PH - 1) * 0.5f;
    const float cx = (float)(PW - 1) * 0.5f;
    float yr   = (yl + 0.5f) * p.inv_sh - 0.5f;
    float dy   = yr - cy;
    float sidy = p.si * dy;
    float cody = p.co * dy;

    #pragma unroll
    for (int i = 0; i < 4; i++) {
        float xl  = xl0 + (float)i;
        bool  vld = (xl >= 0.0f) & (xl < p.sw);

        if (!vld) {
            res[0][i] = img[0][i];
            res[1][i] = img[1][i];
            res[2][i] = img[2][i];
            continue;
        }

        float xr = (xl + 0.5f) * p.inv_sw - 0.5f;
        float dx = xr - cx;
        float xp =  p.co * dx + sidy + cx;
        float yp = -p.si * dx + cody + cy;

        float fy = floorf(yp);
        float fx = floorf(xp);
        float wy = yp - fy;
        float wx = xp - fx;
        int yi = (int)fy;
        int xi = (int)fx;

        bool y0in = (yi >= 0)  & (yi <  PH);
        bool y1in = (yi >= -1) & (yi <  PH - 1);
        bool x0in = (xi >= 0)  & (xi <  PW);
        bool x1in = (xi >= -1) & (xi <  PW - 1);

        int yc0 = min(max(yi,     0), PH - 1);
        int yc1 = min(max(yi + 1, 0), PH - 1);
        int xc0 = min(max(xi,     0), PW - 1);
        int xc1 = min(max(xi + 1, 0), PW - 1);

        float w00 = (1.0f - wy) * (1.0f - wx) * ((y0in & x0in) ? 1.0f : 0.0f);
        float w01 = (1.0f - wy) * wx          * ((y0in & x1in) ? 1.0f : 0.0f);
        float w10 = wy * (1.0f - wx)          * ((y1in & x0in) ? 1.0f : 0.0f);
        float w11 = wy * wx                   * ((y1in & x1in) ? 1.0f : 0.0f);

        int o00 = yc0 * PW + xc0;
        int o01 = yc0 * PW + xc1;
        int o10 = yc1 * PW + xc0;
        int o11 = yc1 * PW + xc1;

        #pragma unroll
        for (int c = 0; c < 3; c++) {
            const float* pc = patch + c * (PH * PW);
            res[c][i] = w00 * __ldg(pc + o00)
                      + w01 * __ldg(pc + o01)
                      + w10 * __ldg(pc + o10)
                      + w11 * __ldg(pc + o11);
        }
    }

    float4 r0 = make_float4(res[0][0], res[0][1], res[0][2], res[0][3]);
    float4 r1 = make_float4(res[1][0], res[1][1], res[1][2], res[1][3]);
    float4 r2 = make_float4(res[2][0], res[2][1], res[2][2], res[2][3]);
    __stcs(out + q0,            r0);
    __stcs(out + q0 + QIMG,     r1);
    __stcs(out + q0 + 2 * QIMG, r2);
}

extern "C" void kernel_launch(void* const* d_in, const int* in_sizes, int n_in,
                              void* d_out, int out_size) {
    const float* images = (const float*)d_in[0];
    const float* patch  = (const float*)d_in[1];
    const float* angles = (const float*)d_in[2];
    const float* scales = (const float*)d_in[3];
    const float* ux     = (const float*)d_in[4];
    const float* uy     = (const float*)d_in[5];
    float* out = (float*)d_out;

    constexpr int QUADS = BB * HH * (WW / 4);   // 6,553,600
    int blocks = QUADS / 256;                   // 25,600
    patch_kernel<<<blocks, 256>>>(
        (const float4*)images, patch, angles, scales, ux, uy, (float4*)out);
}

// round 12
// speedup vs baseline: 1.0238x; 1.0024x over previous
#include <cuda_runtime.h>
#include <math.h>

#define BB 64
#define CC 3
#define HH 640
#define WW 640
#define PH 128
#define PW 128
#define TPB 512

struct BatchParams {
    float y0, x0, sh, sw, inv_sh, inv_sw, co, si;
};

__global__ __launch_bounds__(TPB) void patch_kernel(
    const float4* __restrict__ images,
    const float*  __restrict__ patch,
    const float*  __restrict__ angles,
    const float*  __restrict__ scales,
    const float*  __restrict__ ux,
    const float*  __restrict__ uy,
    float4*       __restrict__ out)
{
    constexpr int QW   = WW / 4;        // 160 quads per row
    constexpr int QIMG = HH * QW;       // 102400 quads per channel (divisible by 512)

    __shared__ BatchParams sp;

    int tid = blockIdx.x * TPB + threadIdx.x;
    int b   = blockIdx.x / (QIMG / TPB);          // uniform per block
    int rem = tid - b * QIMG;
    int y   = rem / QW;
    int xq  = rem - y * QW;

    if (threadIdx.x == 0) {
        float s  = scales[b];
        float sh = floorf((float)PH * s);
        float sw = floorf((float)PW * s);
        BatchParams p;
        p.sh = sh; p.sw = sw;
        p.y0 = floorf(uy[b] * ((float)HH - sh));
        p.x0 = floorf(ux[b] * ((float)WW - sw));
        p.inv_sh = (float)PH / sh;
        p.inv_sw = (float)PW / sw;
        float th = angles[b] * (float)(M_PI / 180.0);
        p.co = cosf(th);
        p.si = sinf(th);
        sp = p;
    }
    __syncthreads();
    BatchParams p = sp;

    float yl  = (float)y - p.y0;
    float xl0 = (float)(xq * 4) - p.x0;
    bool yin  = (yl >= 0.0f) & (yl < p.sh);
    bool xin  = (xl0 + 3.0f >= 0.0f) & (xl0 < p.sw);

    int q0 = b * (CC * QIMG) + y * QW + xq;   // float4 index of channel 0

    if (!(yin & xin)) {
        // Fast path: streaming copy (evict-first both directions)
        float4 v0 = __ldcs(images + q0);
        float4 v1 = __ldcs(images + q0 + QIMG);
        float4 v2 = __ldcs(images + q0 + 2 * QIMG);
        __stcs(out + q0,            v0);
        __stcs(out + q0 + QIMG,     v1);
        __stcs(out + q0 + 2 * QIMG, v2);
        return;
    }

    // Slow path
    bool all_in = (xl0 >= 0.0f) & (xl0 + 3.0f < p.sw);

    float img[3][4];
    if (!all_in) {
        float4 v0 = __ldcs(images + q0);
        float4 v1 = __ldcs(images + q0 + QIMG);
        float4 v2 = __ldcs(images + q0 + 2 * QIMG);
        img[0][0]=v0.x; img[0][1]=v0.y; img[0][2]=v0.z; img[0][3]=v0.w;
        img[1][0]=v1.x; img[1][1]=v1.y; img[1][2]=v1.z; img[1][3]=v1.w;
        img[2][0]=v2.x; img[2][1]=v2.y; img[2][2]=v2.z; img[2][3]=v2.w;
    }
    float res[3][4];

    const float cy = (float)(PH - 1) * 0.5f;
    const float cx = (float)(PW - 1) * 0.5f;
    float yr   = (yl + 0.5f) * p.inv_sh - 0.5f;
    float dy   = yr - cy;
    float sidy = p.si * dy;
    float cody = p.co * dy;

    #pragma unroll
    for (int i = 0; i < 4; i++) {
        float xl  = xl0 + (float)i;
        bool  vld = (xl >= 0.0f) & (xl < p.sw);

        if (!vld) {
            res[0][i] = img[0][i];
            res[1][i] = img[1][i];
            res[2][i] = img[2][i];
            continue;
        }

        float xr = (xl + 0.5f) * p.inv_sw - 0.5f;
        float dx = xr - cx;
        float xp =  p.co * dx + sidy + cx;
        float yp = -p.si * dx + cody + cy;

        float fy = floorf(yp);
        float fx = floorf(xp);
        float wy = yp - fy;
        float wx = xp - fx;
        int yi = (int)fy;
        int xi = (int)fx;

        bool y0in = (yi >= 0)  & (yi <  PH);
        bool y1in = (yi >= -1) & (yi <  PH - 1);
        bool x0in = (xi >= 0)  & (xi <  PW);
        bool x1in = (xi >= -1) & (xi <  PW - 1);

        int yc0 = min(max(yi,     0), PH - 1);
        int yc1 = min(max(yi + 1, 0), PH - 1);
        int xc0 = min(max(xi,     0), PW - 1);
        int xc1 = min(max(xi + 1, 0), PW - 1);

        float w00 = (1.0f - wy) * (1.0f - wx) * ((y0in & x0in) ? 1.0f : 0.0f);
        float w01 = (1.0f - wy) * wx          * ((y0in & x1in) ? 1.0f : 0.0f);
        float w10 = wy * (1.0f - wx)          * ((y1in & x0in) ? 1.0f : 0.0f);
        float w11 = wy * wx                   * ((y1in & x1in) ? 1.0f : 0.0f);

        int o00 = yc0 * PW + xc0;
        int o01 = yc0 * PW + xc1;
        int o10 = yc1 * PW + xc0;
        int o11 = yc1 * PW + xc1;

        #pragma unroll
        for (int c = 0; c < 3; c++) {
            const float* pc = patch + c * (PH * PW);
            res[c][i] = w00 * __ldg(pc + o00)
                      + w01 * __ldg(pc + o01)
                      + w10 * __ldg(pc + o10)
                      + w11 * __ldg(pc + o11);
        }
    }

    float4 r0 = make_float4(res[0][0], res[0][1], res[0][2], res[0][3]);
    float4 r1 = make_float4(res[1][0], res[1][1], res[1][2], res[1][3]);
    float4 r2 = make_float4(res[2][0], res[2][1], res[2][2], res[2][3]);
    __stcs(out + q0,            r0);
    __stcs(out + q0 + QIMG,     r1);
    __stcs(out + q0 + 2 * QIMG, r2);
}

extern "C" void kernel_launch(void* const* d_in, const int* in_sizes, int n_in,
                              void* d_out, int out_size) {
    const float* images = (const float*)d_in[0];
    const float* patch  = (const float*)d_in[1];
    const float* angles = (const float*)d_in[2];
    const float* scales = (const float*)d_in[3];
    const float* ux     = (const float*)d_in[4];
    const float* uy     = (const float*)d_in[5];
    float* out = (float*)d_out;

    constexpr int QUADS = BB * HH * (WW / 4);   // 6,553,600
    int blocks = QUADS / TPB;                   // 12,800
    patch_kernel<<<blocks, TPB>>>(
        (const float4*)images, patch, angles, scales, ux, uy, (float4*)out);
}

// round 13
// speedup vs baseline: 1.0263x; 1.0024x over previous
#include <cuda_runtime.h>
#include <math.h>

#define BB 64
#define CC 3
#define HH 640
#define WW 640
#define PH 128
#define PW 128

struct BatchParams {
    float y0, x0, sh, sw, inv_sh, inv_sw, co, si;
};

__global__ __launch_bounds__(256) void patch_kernel(
    const float4* __restrict__ images,
    const float*  __restrict__ patch,
    const float*  __restrict__ angles,
    const float*  __restrict__ scales,
    const float*  __restrict__ ux,
    const float*  __restrict__ uy,
    float4*       __restrict__ out)
{
    constexpr int QW   = WW / 4;        // 160 quads per row
    constexpr int QIMG = HH * QW;       // 102400 quads per channel (divisible by 256)

    __shared__ BatchParams sp;

    int tid = blockIdx.x * 256 + threadIdx.x;
    int b   = blockIdx.x / (QIMG / 256);          // uniform per block
    int rem = tid - b * QIMG;
    int y   = rem / QW;
    int xq  = rem - y * QW;

    if (threadIdx.x == 0) {
        float s  = scales[b];
        float sh = floorf((float)PH * s);
        float sw = floorf((float)PW * s);
        BatchParams p;
        p.sh = sh; p.sw = sw;
        p.y0 = floorf(uy[b] * ((float)HH - sh));
        p.x0 = floorf(ux[b] * ((float)WW - sw));
        p.inv_sh = (float)PH / sh;
        p.inv_sw = (float)PW / sw;
        float th = angles[b] * (float)(M_PI / 180.0);
        p.co = cosf(th);
        p.si = sinf(th);
        sp = p;
    }
    __syncthreads();
    BatchParams p = sp;

    float yl  = (float)y - p.y0;
    float xl0 = (float)(xq * 4) - p.x0;
    bool yin  = (yl >= 0.0f) & (yl < p.sh);
    bool xin  = (xl0 + 3.0f >= 0.0f) & (xl0 < p.sw);

    int q0 = b * (CC * QIMG) + y * QW + xq;   // float4 index of channel 0

    if (!(yin & xin)) {
        // Fast path: streaming copy (evict-first both directions)
        float4 v0 = __ldcs(images + q0);
        float4 v1 = __ldcs(images + q0 + QIMG);
        float4 v2 = __ldcs(images + q0 + 2 * QIMG);
        __stcs(out + q0,            v0);
        __stcs(out + q0 + QIMG,     v1);
        __stcs(out + q0 + 2 * QIMG, v2);
        return;
    }

    // Slow path
    bool all_in = (xl0 >= 0.0f) & (xl0 + 3.0f < p.sw);

    float img[3][4];
    if (!all_in) {
        float4 v0 = __ldcs(images + q0);
        float4 v1 = __ldcs(images + q0 + QIMG);
        float4 v2 = __ldcs(images + q0 + 2 * QIMG);
        img[0][0]=v0.x; img[0][1]=v0.y; img[0][2]=v0.z; img[0][3]=v0.w;
        img[1][0]=v1.x; img[1][1]=v1.y; img[1][2]=v1.z; img[1][3]=v1.w;
        img[2][0]=v2.x; img[2][1]=v2.y; img[2][2]=v2.z; img[2][3]=v2.w;
    }
    float res[3][4];

    const float cy = (float)(PH - 1) * 0.5f;
    const float cx = (float)(PW - 1) * 0.5f;
    float yr   = (yl + 0.5f) * p.inv_sh - 0.5f;
    float dy   = yr - cy;
    float sidy = p.si * dy;
    float cody = p.co * dy;

    #pragma unroll
    for (int i = 0; i < 4; i++) {
        float xl  = xl0 + (float)i;
        bool  vld = (xl >= 0.0f) & (xl < p.sw);

        if (!vld) {
            res[0][i] = img[0][i];
            res[1][i] = img[1][i];
            res[2][i] = img[2][i];
            continue;
        }

        float xr = (xl + 0.5f) * p.inv_sw - 0.5f;
        float dx = xr - cx;
        float xp =  p.co * dx + sidy + cx;
        float yp = -p.si * dx + cody + cy;

        float fy = floorf(yp);
        float fx = floorf(xp);
        float wy = yp - fy;
        float wx = xp - fx;
        int yi = (int)fy;
        int xi = (int)fx;

        bool y0in = (yi >= 0)  & (yi <  PH);
        bool y1in = (yi >= -1) & (yi <  PH - 1);
        bool x0in = (xi >= 0)  & (xi <  PW);
        bool x1in = (xi >= -1) & (xi <  PW - 1);

        int yc0 = min(max(yi,     0), PH - 1);
        int yc1 = min(max(yi + 1, 0), PH - 1);
        int xc0 = min(max(xi,     0), PW - 1);
        int xc1 = min(max(xi + 1, 0), PW - 1);

        float w00 = (1.0f - wy) * (1.0f - wx) * ((y0in & x0in) ? 1.0f : 0.0f);
        float w01 = (1.0f - wy) * wx          * ((y0in & x1in) ? 1.0f : 0.0f);
        float w10 = wy * (1.0f - wx)          * ((y1in & x0in) ? 1.0f : 0.0f);
        float w11 = wy * wx                   * ((y1in & x1in) ? 1.0f : 0.0f);

        int o00 = yc0 * PW + xc0;
        int o01 = yc0 * PW + xc1;
        int o10 = yc1 * PW + xc0;
        int o11 = yc1 * PW + xc1;

        #pragma unroll
        for (int c = 0; c < 3; c++) {
            const float* pc = patch + c * (PH * PW);
            res[c][i] = w00 * __ldg(pc + o00)
                      + w01 * __ldg(pc + o01)
                      + w10 * __ldg(pc + o10)
                      + w11 * __ldg(pc + o11);
        }
    }

    float4 r0 = make_float4(res[0][0], res[0][1], res[0][2], res[0][3]);
    float4 r1 = make_float4(res[1][0], res[1][1], res[1][2], res[1][3]);
    float4 r2 = make_float4(res[2][0], res[2][1], res[2][2], res[2][3]);
    __stcs(out + q0,            r0);
    __stcs(out + q0 + QIMG,     r1);
    __stcs(out + q0 + 2 * QIMG, r2);
}

extern "C" void kernel_launch(void* const* d_in, const int* in_sizes, int n_in,
                              void* d_out, int out_size) {
    const float* images = (const float*)d_in[0];
    const float* patch  = (const float*)d_in[1];
    const float* angles = (const float*)d_in[2];
    const float* scales = (const float*)d_in[3];
    const float* ux     = (const float*)d_in[4];
    const float* uy     = (const float*)d_in[5];
    float* out = (float*)d_out;

    constexpr int QUADS = BB * HH * (WW / 4);   // 6,553,600
    int blocks = QUADS / 256;                   // 25,600
    patch_kernel<<<blocks, 256>>>(
        (const float4*)images, patch, angles, scales, ux, uy, (float4*)out);
}